// round 3
// baseline (speedup 1.0000x reference)
#include <cuda_runtime.h>
#include <cstdint>
#include <cstddef>

// Problem constants (fixed shapes for this problem)
#define S_MAX   4096
#define D_DIM   256
#define NH      8
#define HD      32
#define H_DIM   256
#define NEG_BIG (-3.402823466e38f)

// ---------------- device scratch (no cudaMalloc allowed) ----------------
__device__ float g_q[S_MAX * H_DIM];              // q = queries@Wq + bq
__device__ float g_qk[S_MAX * NH * D_DIM];        // qk[s][h][j]
__device__ float g_qb[S_MAX * NH];                // qb[s][h]
__device__ float g_Ahat[S_MAX * NH * D_DIM];      // A/denom
__device__ float g_pooled[S_MAX * H_DIM];
__device__ int   g_off[S_MAX + 1];

// ---------------- K0: segment offsets via binary search (idx sorted) ----
__global__ void k_offsets(const int* __restrict__ map, int N, int S) {
    int s = blockIdx.x * blockDim.x + threadIdx.x;
    if (s > S) return;
    int lo = 0, hi = N;
    while (lo < hi) {
        int mid = (lo + hi) >> 1;
        if (map[mid] < s) lo = mid + 1; else hi = mid;
    }
    g_off[s] = lo;
}

// ---------------- tiled GEMM 128x64, 8x4 microtile: C = A@B + bias ------
__global__ void __launch_bounds__(256)
k_gemm_bias(const float* __restrict__ A, const float* __restrict__ B,
            const float* __restrict__ bias, float* __restrict__ C,
            int M, int K, int N) {
    __shared__ float As[16][128];
    __shared__ float Bs[16][68];
    int t  = threadIdx.x;
    int bm = blockIdx.x * 128, bn = blockIdx.y * 64;
    int tx = t & 15, ty = t >> 4;          // ty: 8-row group, tx: 4-col group
    float acc[8][4] = {};
    int ar = t >> 1,  ac8 = (t & 1) * 8;   // A load: row ar, k-offset ac8
    int br = t >> 4,  bc4 = (t & 15) * 4;
    for (int k0 = 0; k0 < K; k0 += 16) {
        float4 av0 = *(const float4*)&A[(size_t)(bm + ar) * K + k0 + ac8];
        float4 av1 = *(const float4*)&A[(size_t)(bm + ar) * K + k0 + ac8 + 4];
        As[ac8 + 0][ar] = av0.x; As[ac8 + 1][ar] = av0.y;
        As[ac8 + 2][ar] = av0.z; As[ac8 + 3][ar] = av0.w;
        As[ac8 + 4][ar] = av1.x; As[ac8 + 5][ar] = av1.y;
        As[ac8 + 6][ar] = av1.z; As[ac8 + 7][ar] = av1.w;
        *(float4*)&Bs[br][bc4] = *(const float4*)&B[(size_t)(k0 + br) * N + bn + bc4];
        __syncthreads();
#pragma unroll
        for (int k = 0; k < 16; k++) {
            float4 ra0 = *(float4*)&As[k][ty * 8];
            float4 ra1 = *(float4*)&As[k][ty * 8 + 4];
            float4 rb  = *(float4*)&Bs[k][tx * 4];
            float ra[8] = {ra0.x, ra0.y, ra0.z, ra0.w, ra1.x, ra1.y, ra1.z, ra1.w};
#pragma unroll
            for (int i = 0; i < 8; i++) {
                acc[i][0] += ra[i] * rb.x;
                acc[i][1] += ra[i] * rb.y;
                acc[i][2] += ra[i] * rb.z;
                acc[i][3] += ra[i] * rb.w;
            }
        }
        __syncthreads();
    }
    float4 bv = *(const float4*)&bias[bn + tx * 4];
#pragma unroll
    for (int i = 0; i < 8; i++) {
        int row = bm + ty * 8 + i;
        float4 o;
        o.x = acc[i][0] + bv.x; o.y = acc[i][1] + bv.y;
        o.z = acc[i][2] + bv.z; o.w = acc[i][3] + bv.w;
        *(float4*)&C[(size_t)row * N + bn + tx * 4] = o;
    }
}

// ---------------- K2: qk[s][h][j] = sum_d q[s][h*32+d]*Wk[j][h*32+d] ----
__global__ void __launch_bounds__(256)
k_qk(const float* __restrict__ Wkv, const float* __restrict__ bkv) {
    int s0 = blockIdx.x * 32, h = blockIdx.y;
    int t = threadIdx.x;
    __shared__ float sQ[32][36];
    __shared__ float sW[256][36];
    __shared__ float sBk[32];
    {   // load q slice [32 s][32 d]
        int s = t >> 3, d4 = (t & 7) * 4;
        float4 v = *(const float4*)&g_q[(size_t)(s0 + s) * H_DIM + h * HD + d4];
        sQ[s][d4 + 0] = v.x; sQ[s][d4 + 1] = v.y;
        sQ[s][d4 + 2] = v.z; sQ[s][d4 + 3] = v.w;
    }
    if (t < 32) sBk[t] = bkv[h * HD + t];
    {   // load Wk slice [256 j][32 d], coalesced on d
        int d = t & 31;
        for (int j = t >> 5; j < 256; j += 8)
            sW[j][d] = Wkv[(size_t)j * 512 + h * HD + d];
    }
    __syncthreads();
    float wreg[32];
#pragma unroll
    for (int i = 0; i < 8; i++) {
        float4 v = *(float4*)&sW[t][i * 4];
        wreg[i * 4 + 0] = v.x; wreg[i * 4 + 1] = v.y;
        wreg[i * 4 + 2] = v.z; wreg[i * 4 + 3] = v.w;
    }
    float* outp = g_qk + (size_t)s0 * (NH * D_DIM) + h * D_DIM + t;
    for (int s = 0; s < 32; s++) {
        float acc = 0.f;
#pragma unroll
        for (int d = 0; d < 32; d++) acc += sQ[s][d] * wreg[d];
        outp[(size_t)s * (NH * D_DIM)] = acc;
    }
    if (t < 32) {
        float acc = 0.f;
#pragma unroll
        for (int d = 0; d < 32; d++) acc += sQ[t][d] * sBk[d];
        g_qb[(s0 + t) * NH + h] = acc;
    }
}

// ---------------- K3: streaming online-softmax accumulation -------------
// One block per sample. Score phase: warps split the j axis (E read once).
// A-update: thread owns 4 columns; the 32-element tile is split 4 ways
// across thread groups (g = t>>6 handles elements [8g,8g+8)); per-group
// partial accumulators carried across all tiles (rescale commutes), reduced
// once through smem at the end.
__global__ void __launch_bounds__(256)
k_attn(const float* __restrict__ emb, float scale) {
    int s = blockIdx.x;
    int t = threadIdx.x;
    int lane = t & 31, w = t >> 5;
    int grp = t >> 6, cq = t & 63;        // A-update: 4 cols at cq*4, elems [8g,8g+8)

    __shared__ float sQK[NH][260];
    __shared__ float sE[32][260];          // reused as reduction buffer at end
    __shared__ float sPart[32 * 65 + 16];  // [e*65 + h*8 + w]
    __shared__ float sP[32][12];
    __shared__ float sF[NH];
    __shared__ float sD[NH];
    __shared__ float sQBs[NH];

    const float* qkp = g_qk + (size_t)s * (NH * D_DIM);
    for (int i = t; i < (NH * D_DIM) / 4; i += 256) {
        float4 v = *(const float4*)(qkp + i * 4);
        int h = i >> 6, j = (i * 4) & 255;
        *(float4*)&sQK[h][j] = v;
    }
    if (t < NH) sQBs[t] = g_qb[s * NH + t];

    int start = g_off[s], end = g_off[s + 1];
    float a[NH][4];
#pragma unroll
    for (int h = 0; h < NH; h++)
#pragma unroll
        for (int c = 0; c < 4; c++) a[h][c] = 0.f;
    float m_w = NEG_BIG, d_w = 0.f;
    int j0 = w * 32;
    __syncthreads();

    for (int t0 = start; t0 < end; t0 += 32) {
        int T = min(32, end - t0);
        // load embedding tile (coalesced float4)
        for (int i = t; i < T * 64; i += 256) {
            int e = i >> 6, j4 = (i & 63) * 4;
            *(float4*)&sE[e][j4] = *(const float4*)(emb + (size_t)(t0 + e) * D_DIM + j4);
        }
        __syncthreads();

        // ---- score partials: warp w covers j in [j0, j0+32), lane = element
        {
            float acc[NH];
#pragma unroll
            for (int h = 0; h < NH; h++) acc[h] = 0.f;
#pragma unroll
            for (int half = 0; half < 2; half++) {
                float4 er[4];
#pragma unroll
                for (int q = 0; q < 4; q++)
                    er[q] = *(float4*)&sE[lane][j0 + half * 16 + q * 4];
#pragma unroll
                for (int h = 0; h < NH; h++) {
#pragma unroll
                    for (int q = 0; q < 4; q++) {
                        float4 qv = *(float4*)&sQK[h][j0 + half * 16 + q * 4];
                        acc[h] += er[q].x * qv.x + er[q].y * qv.y
                                + er[q].z * qv.z + er[q].w * qv.w;
                    }
                }
            }
#pragma unroll
            for (int h = 0; h < NH; h++)
                sPart[lane * 65 + h * 8 + w] = acc[h];
        }
        __syncthreads();

        // ---- reduce partials: thread (lane=e, w=h)
        float sc = NEG_BIG, p = 0.f;
        if (lane < T) {
            float sum = 0.f;
#pragma unroll
            for (int i = 0; i < 8; i++) sum += sPart[lane * 65 + w * 8 + i];
            sc = scale * (sum + sQBs[w]);
        }
        float mt = sc;
#pragma unroll
        for (int o = 16; o; o >>= 1) mt = fmaxf(mt, __shfl_xor_sync(0xffffffffu, mt, o));
        float mnew = fmaxf(m_w, mt);
        float factor = __expf(m_w - mnew);
        if (lane < T) p = __expf(sc - mnew);
        sP[lane][w] = p;
        float ps = p;
#pragma unroll
        for (int o = 16; o; o >>= 1) ps += __shfl_xor_sync(0xffffffffu, ps, o);
        d_w = d_w * factor + ps;
        m_w = mnew;
        if (lane == 0) sF[w] = factor;
        __syncthreads();

        // ---- A update: group grp handles elements [8*grp, 8*grp+8) over
        //      this thread's 4 columns [cq*4, cq*4+4)
        {
#pragma unroll
            for (int h = 0; h < NH; h++) {
                float f = sF[h];
#pragma unroll
                for (int c = 0; c < 4; c++) a[h][c] *= f;
            }
            int e0 = grp * 8, e1 = min(e0 + 8, T);
            for (int e = e0; e < e1; e++) {
                float4 p0 = *(float4*)&sP[e][0];
                float4 p1 = *(float4*)&sP[e][4];
                float4 ev = *(float4*)&sE[e][cq * 4];
                a[0][0] += p0.x * ev.x; a[0][1] += p0.x * ev.y; a[0][2] += p0.x * ev.z; a[0][3] += p0.x * ev.w;
                a[1][0] += p0.y * ev.x; a[1][1] += p0.y * ev.y; a[1][2] += p0.y * ev.z; a[1][3] += p0.y * ev.w;
                a[2][0] += p0.z * ev.x; a[2][1] += p0.z * ev.y; a[2][2] += p0.z * ev.z; a[2][3] += p0.z * ev.w;
                a[3][0] += p0.w * ev.x; a[3][1] += p0.w * ev.y; a[3][2] += p0.w * ev.z; a[3][3] += p0.w * ev.w;
                a[4][0] += p1.x * ev.x; a[4][1] += p1.x * ev.y; a[4][2] += p1.x * ev.z; a[4][3] += p1.x * ev.w;
                a[5][0] += p1.y * ev.x; a[5][1] += p1.y * ev.y; a[5][2] += p1.y * ev.z; a[5][3] += p1.y * ev.w;
                a[6][0] += p1.z * ev.x; a[6][1] += p1.z * ev.y; a[6][2] += p1.z * ev.z; a[6][3] += p1.z * ev.w;
                a[7][0] += p1.w * ev.x; a[7][1] += p1.w * ev.y; a[7][2] += p1.w * ev.z; a[7][3] += p1.w * ev.w;
            }
        }
        __syncthreads();
    }

    // ---- epilogue: stage 4-group partials in smem (reusing sE), reduce,
    //      normalize by denom, write Ahat.
    if (lane == 0) sD[w] = d_w;
    float* buf = &sE[0][0];                // 8320 floats >= 8*4*256
#pragma unroll
    for (int h = 0; h < NH; h++) {
        float4 v;
        v.x = a[h][0]; v.y = a[h][1]; v.z = a[h][2]; v.w = a[h][3];
        *(float4*)&buf[h * 1024 + grp * 256 + cq * 4] = v;
    }
    __syncthreads();
    float* outp = g_Ahat + (size_t)s * (NH * D_DIM);
#pragma unroll
    for (int h = 0; h < NH; h++) {
        float dh = sD[h];
        float rdh = (dh > 0.f) ? (1.0f / dh) : 0.f;
        float v = buf[h * 1024 + t] + buf[h * 1024 + 256 + t]
                + buf[h * 1024 + 512 + t] + buf[h * 1024 + 768 + t];
        outp[h * D_DIM + t] = v * rdh;
    }
}

// ---------------- K4: pooled = Ahat @ Wv (+ bv if nonempty) -------------
__global__ void __launch_bounds__(256)
k_pool(const float* __restrict__ Wkv, const float* __restrict__ bkv) {
    int s0 = blockIdx.x * 32, h = blockIdx.y;
    int t = threadIdx.x;
    __shared__ float sA[32][132];
    __shared__ float sWt[32][132];   // sWt[d][j] = Wv[j][h*32+d]
    float acc[4] = {0.f, 0.f, 0.f, 0.f};
    int d = t & 31, sl0 = (t >> 5) * 4;

    for (int jc = 0; jc < 2; jc++) {
        for (int i = t; i < 32 * 32; i += 256) {
            int r = i >> 5, j4 = (i & 31) * 4;
            *(float4*)&sA[r][j4] =
                *(const float4*)&g_Ahat[(size_t)(s0 + r) * (NH * D_DIM) + h * D_DIM + jc * 128 + j4];
        }
        {
            int dd = t & 31;
            for (int j = t >> 5; j < 128; j += 8)
                sWt[dd][j] = Wkv[(size_t)(jc * 128 + j) * 512 + 256 + h * HD + dd];
        }
        __syncthreads();
#pragma unroll
        for (int j4 = 0; j4 < 32; j4++) {
            float4 wv = *(float4*)&sWt[d][j4 * 4];
#pragma unroll
            for (int q = 0; q < 4; q++) {
                float4 av = *(float4*)&sA[sl0 + q][j4 * 4];
                acc[q] += av.x * wv.x + av.y * wv.y + av.z * wv.z + av.w * wv.w;
            }
        }
        __syncthreads();
    }
    float bv = bkv[256 + h * HD + d];
#pragma unroll
    for (int q = 0; q < 4; q++) {
        int srow = s0 + sl0 + q;
        float ne = (g_off[srow + 1] > g_off[srow]) ? bv : 0.f;
        g_pooled[(size_t)srow * H_DIM + h * HD + d] = acc[q] + ne;
    }
}

// ---------------- launch ----------------
extern "C" void kernel_launch(void* const* d_in, const int* in_sizes, int n_in,
                              void* d_out, int out_size) {
    const float* queries = (const float*)d_in[0];
    const float* emb     = (const float*)d_in[1];
    const int*   map     = (const int*)  d_in[2];
    // num_samples may or may not be materialized as a device input
    int base = (n_in >= 10 && in_sizes[3] < 16) ? 4 : 3;
    const float* Wq  = (const float*)d_in[base + 0];
    const float* bq  = (const float*)d_in[base + 1];
    const float* Wkv = (const float*)d_in[base + 2];
    const float* bkv = (const float*)d_in[base + 3];
    const float* Wo  = (const float*)d_in[base + 4];
    const float* bo  = (const float*)d_in[base + 5];
    float* out = (float*)d_out;

    int S = in_sizes[0] / D_DIM;     // 4096
    int N = in_sizes[1] / D_DIM;     // 262144
    float scale = 0.17677669529663687f;   // 1/sqrt(32)

    float* dq      = nullptr; cudaGetSymbolAddress((void**)&dq,      g_q);
    float* dpooled = nullptr; cudaGetSymbolAddress((void**)&dpooled, g_pooled);

    // K0: segment offsets
    k_offsets<<<(S + 1 + 255) / 256, 256>>>(map, N, S);
    // K1: q projection
    {
        dim3 grid(S / 128, H_DIM / 64);
        k_gemm_bias<<<grid, 256>>>(queries, Wq, bq, dq, S, D_DIM, H_DIM);
    }
    // K2: qk/qb precompute
    {
        dim3 grid(S / 32, NH);
        k_qk<<<grid, 256>>>(Wkv, bkv);
    }
    // K3: streaming attention accumulation
    k_attn<<<S, 256>>>(emb, scale);
    // K4: pooled projection through Wv
    {
        dim3 grid(S / 32, NH);
        k_pool<<<grid, 256>>>(Wkv, bkv);
    }
    // K5: output projection
    {
        dim3 grid(S / 128, H_DIM / 64);
        k_gemm_bias<<<grid, 256>>>(dpooled, Wo, bo, out, S, H_DIM, H_DIM);
    }
}

// round 4
// speedup vs baseline: 1.1023x; 1.1023x over previous
#include <cuda_runtime.h>
#include <cstdint>
#include <cstddef>

// Problem constants (fixed shapes for this problem)
#define S_MAX   4096
#define D_DIM   256
#define NH      8
#define HD      32
#define H_DIM   256
#define NEG_BIG (-3.402823466e38f)

// ---------------- device scratch (no cudaMalloc allowed) ----------------
__device__ float g_q[S_MAX * H_DIM];              // q = queries@Wq + bq
__device__ float g_qk[S_MAX * NH * D_DIM];        // qk[s][h][j]
__device__ float g_qb[S_MAX * NH];                // qb[s][h]
__device__ float g_Ahat[S_MAX * NH * D_DIM];      // A/denom
__device__ float g_pooled[S_MAX * H_DIM];
__device__ int   g_off[S_MAX + 1];

// ---------------- cp.async helpers ----------------
__device__ __forceinline__ void cpa16(float* dst, const float* src) {
    uint32_t d = (uint32_t)__cvta_generic_to_shared(dst);
    asm volatile("cp.async.cg.shared.global [%0], [%1], 16;" :: "r"(d), "l"(src));
}
#define CPA_COMMIT() asm volatile("cp.async.commit_group;")
#define CPA_WAIT0()  asm volatile("cp.async.wait_group 0;")

// ---------------- K0: segment offsets via binary search (idx sorted) ----
__global__ void k_offsets(const int* __restrict__ map, int N, int S) {
    int s = blockIdx.x * blockDim.x + threadIdx.x;
    if (s > S) return;
    int lo = 0, hi = N;
    while (lo < hi) {
        int mid = (lo + hi) >> 1;
        if (map[mid] < s) lo = mid + 1; else hi = mid;
    }
    g_off[s] = lo;
}

// ---------------- generic tiled GEMM 64x64: C = A[MxK] @ B[KxN] + bias --
__global__ void __launch_bounds__(256)
k_gemm_bias(const float* __restrict__ A, const float* __restrict__ B,
            const float* __restrict__ bias, float* __restrict__ C,
            int M, int K, int N) {
    __shared__ float As[16][64];
    __shared__ float Bs[16][68];
    int t  = threadIdx.x;
    int bm = blockIdx.x * 64, bn = blockIdx.y * 64;
    int tx = t & 15, ty = t >> 4;
    float acc[4][4] = {};
    int ar = t >> 2,  ac4 = (t & 3)  * 4;
    int br = t >> 4,  bc4 = (t & 15) * 4;
    for (int k0 = 0; k0 < K; k0 += 16) {
        float4 av = *(const float4*)&A[(size_t)(bm + ar) * K + k0 + ac4];
        As[ac4 + 0][ar] = av.x; As[ac4 + 1][ar] = av.y;
        As[ac4 + 2][ar] = av.z; As[ac4 + 3][ar] = av.w;
        *(float4*)&Bs[br][bc4] = *(const float4*)&B[(size_t)(k0 + br) * N + bn + bc4];
        __syncthreads();
#pragma unroll
        for (int k = 0; k < 16; k++) {
            float ra[4], rb[4];
#pragma unroll
            for (int i = 0; i < 4; i++) ra[i] = As[k][ty * 4 + i];
#pragma unroll
            for (int j = 0; j < 4; j++) rb[j] = Bs[k][tx * 4 + j];
#pragma unroll
            for (int i = 0; i < 4; i++)
#pragma unroll
                for (int j = 0; j < 4; j++)
                    acc[i][j] += ra[i] * rb[j];
        }
        __syncthreads();
    }
#pragma unroll
    for (int i = 0; i < 4; i++) {
        int row = bm + ty * 4 + i;
#pragma unroll
        for (int j = 0; j < 4; j++) {
            int col = bn + tx * 4 + j;
            C[(size_t)row * N + col] = acc[i][j] + bias[col];
        }
    }
}

// ---------------- K2: qk[s][h][j] = sum_d q[s][h*32+d]*Wk[j][h*32+d] ----
__global__ void __launch_bounds__(256)
k_qk(const float* __restrict__ Wkv, const float* __restrict__ bkv) {
    int s0 = blockIdx.x * 32, h = blockIdx.y;
    int t = threadIdx.x;
    __shared__ float sQ[32][36];
    __shared__ float sW[256][36];
    __shared__ float sBk[32];
    {   // load q slice [32 s][32 d]
        int s = t >> 3, d4 = (t & 7) * 4;
        float4 v = *(const float4*)&g_q[(size_t)(s0 + s) * H_DIM + h * HD + d4];
        sQ[s][d4 + 0] = v.x; sQ[s][d4 + 1] = v.y;
        sQ[s][d4 + 2] = v.z; sQ[s][d4 + 3] = v.w;
    }
    if (t < 32) sBk[t] = bkv[h * HD + t];
    {   // load Wk slice [256 j][32 d], coalesced on d
        int d = t & 31;
        for (int j = t >> 5; j < 256; j += 8)
            sW[j][d] = Wkv[(size_t)j * 512 + h * HD + d];
    }
    __syncthreads();
    float wreg[32];
#pragma unroll
    for (int i = 0; i < 8; i++) {
        float4 v = *(float4*)&sW[t][i * 4];
        wreg[i * 4 + 0] = v.x; wreg[i * 4 + 1] = v.y;
        wreg[i * 4 + 2] = v.z; wreg[i * 4 + 3] = v.w;
    }
    float* outp = g_qk + (size_t)s0 * (NH * D_DIM) + h * D_DIM + t;
    for (int s = 0; s < 32; s++) {
        float acc = 0.f;
#pragma unroll
        for (int d = 0; d < 32; d++) acc += sQ[s][d] * wreg[d];
        outp[(size_t)s * (NH * D_DIM)] = acc;
    }
    if (t < 32) {
        float acc = 0.f;
#pragma unroll
        for (int d = 0; d < 32; d++) acc += sQ[t][d] * sBk[d];
        g_qb[(s0 + t) * NH + h] = acc;
    }
}

// ---------------- K3: streaming online-softmax accumulation -------------
// One block per sample. cp.async double-buffered emb tiles: tile t+1 streams
// into the other buffer while tile t's score/softmax/A-update run. Score
// phase splits the j axis across warps (E read once); A-update is the R2
// 1-column-per-thread layout (best measured occupancy/latency balance).
// Dynamic smem (~85KB) layout in floats:
//   [0,2080)            sQK   8 x 260
//   [2080,18720)        sE    2 buffers x 32 x 260
//   [18720,20816)       sPart 32*65+16
//   [20816,21200)       sP    32 x 12
//   [21200..]           sF[8], sD[8], sQBs[8]
#define ATTN_SMEM_FLOATS (21224)
#define SE_STRIDE 260
#define SE_BUF    (32 * SE_STRIDE)

__global__ void __launch_bounds__(256)
k_attn(const float* __restrict__ emb, float scale) {
    extern __shared__ float dyn[];
    float* sQK   = dyn;                    // [h*260 + j]
    float* sEb   = dyn + 2080;             // two buffers
    float* sPart = dyn + 18720;            // [e*65 + h*8 + w]
    float* sP    = dyn + 20816;            // [e*12 + h]
    float* sF    = dyn + 21200;
    float* sD    = dyn + 21208;
    float* sQBs  = dyn + 21216;

    int s = blockIdx.x;
    int t = threadIdx.x;
    int lane = t & 31, w = t >> 5;

    int start = g_off[s], end = g_off[s + 1];

    // prefetch first emb tile before anything else (overlaps qk load)
    if (start < end) {
        int T = min(32, end - start);
        for (int i = t; i < T * 64; i += 256) {
            int e = i >> 6, j4 = (i & 63) * 4;
            cpa16(&sEb[e * SE_STRIDE + j4],
                  emb + (size_t)(start + e) * D_DIM + j4);
        }
    }
    CPA_COMMIT();

    const float* qkp = g_qk + (size_t)s * (NH * D_DIM);
    for (int i = t; i < (NH * D_DIM) / 4; i += 256) {
        float4 v = *(const float4*)(qkp + i * 4);
        int h = i >> 6, j = (i * 4) & 255;
        *(float4*)&sQK[h * SE_STRIDE + j] = v;
    }
    if (t < NH) sQBs[t] = g_qb[s * NH + t];

    float a[NH];
#pragma unroll
    for (int i = 0; i < NH; i++) a[i] = 0.f;
    float m_w = NEG_BIG, d_w = 0.f;
    int j0 = w * 32;
    __syncthreads();   // sQK ready

    int b = 0;
    for (int t0 = start; t0 < end; t0 += 32, b ^= 1) {
        int T = min(32, end - t0);
        float* sE = sEb + b * SE_BUF;

        CPA_WAIT0();
        __syncthreads();   // buffer b full; all prior-phase reads done

        // issue prefetch of next tile into the other buffer
        if (t0 + 32 < end) {
            int Tn = min(32, end - (t0 + 32));
            float* sEn = sEb + (b ^ 1) * SE_BUF;
            for (int i = t; i < Tn * 64; i += 256) {
                int e = i >> 6, j4 = (i & 63) * 4;
                cpa16(&sEn[e * SE_STRIDE + j4],
                      emb + (size_t)(t0 + 32 + e) * D_DIM + j4);
            }
        }
        CPA_COMMIT();

        // ---- score partials: warp w covers j in [j0, j0+32), lane = element
        {
            float acc[NH];
#pragma unroll
            for (int h = 0; h < NH; h++) acc[h] = 0.f;
#pragma unroll
            for (int half = 0; half < 2; half++) {
                float4 er[4];
#pragma unroll
                for (int q = 0; q < 4; q++)
                    er[q] = *(float4*)&sE[lane * SE_STRIDE + j0 + half * 16 + q * 4];
#pragma unroll
                for (int h = 0; h < NH; h++) {
#pragma unroll
                    for (int q = 0; q < 4; q++) {
                        float4 qv = *(float4*)&sQK[h * SE_STRIDE + j0 + half * 16 + q * 4];
                        acc[h] += er[q].x * qv.x + er[q].y * qv.y
                                + er[q].z * qv.z + er[q].w * qv.w;
                    }
                }
            }
#pragma unroll
            for (int h = 0; h < NH; h++)
                sPart[lane * 65 + h * 8 + w] = acc[h];
        }
        __syncthreads();

        // ---- reduce partials: thread (lane=e, w=h)
        float sc = NEG_BIG, p = 0.f;
        if (lane < T) {
            float sum = 0.f;
#pragma unroll
            for (int i = 0; i < 8; i++) sum += sPart[lane * 65 + w * 8 + i];
            sc = scale * (sum + sQBs[w]);
        }
        float mt = sc;
#pragma unroll
        for (int o = 16; o; o >>= 1) mt = fmaxf(mt, __shfl_xor_sync(0xffffffffu, mt, o));
        float mnew = fmaxf(m_w, mt);
        float factor = __expf(m_w - mnew);
        if (lane < T) p = __expf(sc - mnew);
        sP[lane * 12 + w] = p;
        float ps = p;
#pragma unroll
        for (int o = 16; o; o >>= 1) ps += __shfl_xor_sync(0xffffffffu, ps, o);
        d_w = d_w * factor + ps;
        m_w = mnew;
        if (lane == 0) sF[w] = factor;
        __syncthreads();

        // ---- A update: thread owns column j = t for all 8 heads
#pragma unroll
        for (int h = 0; h < NH; h++) a[h] *= sF[h];
        for (int e = 0; e < T; e++) {
            float4 p0 = *(float4*)&sP[e * 12 + 0];
            float4 p1 = *(float4*)&sP[e * 12 + 4];
            float ev = sE[e * SE_STRIDE + t];
            a[0] += p0.x * ev; a[1] += p0.y * ev; a[2] += p0.z * ev; a[3] += p0.w * ev;
            a[4] += p1.x * ev; a[5] += p1.y * ev; a[6] += p1.z * ev; a[7] += p1.w * ev;
        }
        // no barrier here: next iteration's top wait+sync covers it
    }

    if (lane == 0) sD[w] = d_w;
    __syncthreads();
    float* outp = g_Ahat + (size_t)s * (NH * D_DIM);
#pragma unroll
    for (int h = 0; h < NH; h++) {
        float dh = sD[h];
        outp[h * D_DIM + t] = (dh > 0.f) ? (a[h] / dh) : 0.f;
    }
}

// ---------------- K4: pooled = Ahat @ Wv (+ bv if nonempty) -------------
__global__ void __launch_bounds__(256)
k_pool(const float* __restrict__ Wkv, const float* __restrict__ bkv) {
    int s0 = blockIdx.x * 32, h = blockIdx.y;
    int t = threadIdx.x;
    __shared__ float sA[32][132];
    __shared__ float sWt[32][132];   // sWt[d][j] = Wv[j][h*32+d]
    float acc[4] = {0.f, 0.f, 0.f, 0.f};
    int d = t & 31, sl0 = (t >> 5) * 4;

    for (int jc = 0; jc < 2; jc++) {
        for (int i = t; i < 32 * 32; i += 256) {
            int r = i >> 5, j4 = (i & 31) * 4;
            *(float4*)&sA[r][j4] =
                *(const float4*)&g_Ahat[(size_t)(s0 + r) * (NH * D_DIM) + h * D_DIM + jc * 128 + j4];
        }
        {
            int dd = t & 31;
            for (int j = t >> 5; j < 128; j += 8)
                sWt[dd][j] = Wkv[(size_t)(jc * 128 + j) * 512 + 256 + h * HD + dd];
        }
        __syncthreads();
#pragma unroll
        for (int j4 = 0; j4 < 32; j4++) {
            float4 wv = *(float4*)&sWt[d][j4 * 4];
#pragma unroll
            for (int q = 0; q < 4; q++) {
                float4 av = *(float4*)&sA[sl0 + q][j4 * 4];
                acc[q] += av.x * wv.x + av.y * wv.y + av.z * wv.z + av.w * wv.w;
            }
        }
        __syncthreads();
    }
    float bv = bkv[256 + h * HD + d];
#pragma unroll
    for (int q = 0; q < 4; q++) {
        int srow = s0 + sl0 + q;
        float ne = (g_off[srow + 1] > g_off[srow]) ? bv : 0.f;
        g_pooled[(size_t)srow * H_DIM + h * HD + d] = acc[q] + ne;
    }
}

// ---------------- launch ----------------
extern "C" void kernel_launch(void* const* d_in, const int* in_sizes, int n_in,
                              void* d_out, int out_size) {
    const float* queries = (const float*)d_in[0];
    const float* emb     = (const float*)d_in[1];
    const int*   map     = (const int*)  d_in[2];
    // num_samples may or may not be materialized as a device input
    int base = (n_in >= 10 && in_sizes[3] < 16) ? 4 : 3;
    const float* Wq  = (const float*)d_in[base + 0];
    const float* bq  = (const float*)d_in[base + 1];
    const float* Wkv = (const float*)d_in[base + 2];
    const float* bkv = (const float*)d_in[base + 3];
    const float* Wo  = (const float*)d_in[base + 4];
    const float* bo  = (const float*)d_in[base + 5];
    float* out = (float*)d_out;

    int S = in_sizes[0] / D_DIM;     // 4096
    int N = in_sizes[1] / D_DIM;     // 262144
    float scale = 0.17677669529663687f;   // 1/sqrt(32)

    float* dq      = nullptr; cudaGetSymbolAddress((void**)&dq,      g_q);
    float* dpooled = nullptr; cudaGetSymbolAddress((void**)&dpooled, g_pooled);

    cudaFuncSetAttribute(k_attn, cudaFuncAttributeMaxDynamicSharedMemorySize,
                         ATTN_SMEM_FLOATS * 4);

    // K0: segment offsets
    k_offsets<<<(S + 1 + 255) / 256, 256>>>(map, N, S);
    // K1: q projection
    {
        dim3 grid(S / 64, H_DIM / 64);
        k_gemm_bias<<<grid, 256>>>(queries, Wq, bq, dq, S, D_DIM, H_DIM);
    }
    // K2: qk/qb precompute
    {
        dim3 grid(S / 32, NH);
        k_qk<<<grid, 256>>>(Wkv, bkv);
    }
    // K3: streaming attention accumulation (double-buffered cp.async)
    k_attn<<<S, 256, ATTN_SMEM_FLOATS * 4>>>(emb, scale);
    // K4: pooled projection through Wv
    {
        dim3 grid(S / 32, NH);
        k_pool<<<grid, 256>>>(Wkv, bkv);
    }
    // K5: output projection
    {
        dim3 grid(S / 64, H_DIM / 64);
        k_gemm_bias<<<grid, 256>>>(dpooled, Wo, bo, out, S, H_DIM, H_DIM);
    }
}